// round 11
// baseline (speedup 1.0000x reference)
#include <cuda_runtime.h>
#include <math.h>
#include <stdint.h>

#define SEQ   128
#define BATCH 64
#define HID   1024
#define VOCAB 10000
#define TB    (SEQ*BATCH)   /* 8192 */
#define SB    (BATCH*HID)   /* 65536 */

// ---------------- device scratch (no allocations allowed) -------------------
__device__ float g_Xp[TB*HID];          // RAW x_t @ Wx0^T (no bias), all steps
__device__ float g_H1[(SEQ+1)*SB];      // slot t = h1 entering step t (slot 0 = init)
__device__ float g_h0[2*SB];            // h0 ping-pong
__device__ float g_y0[SB];              // y0 = h0 @ Wy0^T + by0
__device__ float g_p0[SB];              // h0 @ Wh0^T            (raw)
__device__ float g_p1[SB];              // y0 @ Wx1^T            (raw)
__device__ float g_p2[SB];              // h1 @ Wh1^T            (raw)

// ---------------- XLA EmitFastTanh, FMA-CONTRACTED (LLVM contract / ptxas fmad)
__device__ __forceinline__ float xla_tanh(float x)
{
    const float kClamp = 7.90531110763549805f;
    float xc = fminf(fmaxf(x, -kClamp), kClamp);
    float x2 = __fmul_rn(xc, xc);
    // numerator Horner, contracted: n = fma(x2, n, alpha_next)
    float n = __fmaf_rn(x2, -2.76076847742355e-16f, 2.00018790482477e-13f);
    n = __fmaf_rn(x2, n, -8.60467152213735e-11f);
    n = __fmaf_rn(x2, n,  5.12229709037114e-08f);
    n = __fmaf_rn(x2, n,  1.48572235717979e-05f);
    n = __fmaf_rn(x2, n,  6.37261928875436e-04f);
    n = __fmaf_rn(x2, n,  4.89352455891786e-03f);
    n = __fmul_rn(xc, n);
    // denominator Horner, contracted
    float d = __fmaf_rn(x2, 1.19825839466702e-06f, 1.18534705686654e-04f);
    d = __fmaf_rn(x2, d, 2.26843463243900e-03f);
    d = __fmaf_rn(x2, d, 4.89352518554385e-03f);
    // |x| < 0.0004 -> passthrough of ORIGINAL x
    return (fabsf(x) < 0.0004f) ? x : __fdiv_rn(n, d);
}

// ---------------- 64x64x16 GEMM: C = op(A) @ B^T (+bias) --------------------
// Sequential-k, single accumulator per output, explicit FMA (matches Eigen /
// cuBLAS-SIMT per-element ascending-k FMA chain). B is [N,K] row-major.
template<bool GATHER, bool BIAS>
__global__ __launch_bounds__(256)
void gemm64t(const float* __restrict__ A, const float* __restrict__ B,
             const float* __restrict__ bias, const int* __restrict__ gidx,
             float* __restrict__ C, int M, int N, int K)
{
    __shared__ float As[16][64];   // [k][m]
    __shared__ float Bs[16][64];   // [k][n]

    const int tid = threadIdx.x;
    const int bm = blockIdx.y * 64;
    const int bn = blockIdx.x * 64;
    const int tx = tid & 15;
    const int ty = tid >> 4;
    const int lr = tid >> 2;
    const int lk = (tid & 3) << 2;

    const bool a_ok = (bm + lr) < M;
    size_t arow = 0;
    if (a_ok) {
        if (GATHER) {
            int gi = gidx[bm + lr];
            if ((unsigned)gi >= (unsigned)VOCAB) gi = 0;
            arow = (size_t)gi;
        } else {
            arow = (size_t)(bm + lr);
        }
    }
    const float* Ap = A + arow * (size_t)K + lk;

    const bool b_ok = (bn + lr) < N;
    const float* Bp = B + (size_t)(b_ok ? (bn + lr) : 0) * K + lk;

    float acc[4][4] = {{0.f}};

    for (int k0 = 0; k0 < K; k0 += 16) {
        float4 va = make_float4(0.f, 0.f, 0.f, 0.f);
        if (a_ok) va = *(const float4*)(Ap + k0);
        As[lk+0][lr] = va.x; As[lk+1][lr] = va.y;
        As[lk+2][lr] = va.z; As[lk+3][lr] = va.w;

        float4 vb = make_float4(0.f, 0.f, 0.f, 0.f);
        if (b_ok) vb = *(const float4*)(Bp + k0);
        Bs[lk+0][lr] = vb.x; Bs[lk+1][lr] = vb.y;
        Bs[lk+2][lr] = vb.z; Bs[lk+3][lr] = vb.w;
        __syncthreads();

        #pragma unroll
        for (int k = 0; k < 16; ++k) {   // ascending k
            float4 a = *(const float4*)&As[k][ty << 2];
            float4 b = *(const float4*)&Bs[k][tx << 2];
            float av[4] = {a.x, a.y, a.z, a.w};
            float bv[4] = {b.x, b.y, b.z, b.w};
            #pragma unroll
            for (int i = 0; i < 4; ++i)
                #pragma unroll
                for (int j = 0; j < 4; ++j)
                    acc[i][j] = __fmaf_rn(av[i], bv[j], acc[i][j]);
        }
        __syncthreads();
    }

    #pragma unroll
    for (int i = 0; i < 4; ++i) {
        int gr = bm + (ty << 2) + i;
        if (gr >= M) continue;
        size_t ro = (size_t)gr * N;
        #pragma unroll
        for (int j = 0; j < 4; ++j) {
            int gc = bn + (tx << 2) + j;
            if (gc < N) {
                float v = acc[i][j];
                if (BIAS) v = __fadd_rn(v, bias[gc]);
                C[ro + gc] = v;
            }
        }
    }
}

// ---------------- per-step small GEMM tile: out[64 x 32cols] = A @ W^T ------
__device__ __forceinline__
void small_gemm_tile(const float* __restrict__ A, const float* __restrict__ W,
                     const float* __restrict__ bias, float* __restrict__ out, int j0)
{
    __shared__ float As[32][64];
    __shared__ float Ws[32][36];

    const int tid = threadIdx.x;
    const int tx = tid & 7;
    const int ty = tid >> 3;

    const int lr = tid >> 2;
    const int lk = (tid & 3) << 2;
    const int wj = tid >> 3;
    const int wk = (tid & 7) << 2;

    float acc[2][4] = {{0.f}};

    for (int kb = 0; kb < HID; kb += 32) {
        #pragma unroll
        for (int h = 0; h < 32; h += 16) {
            float4 va = *(const float4*)&A[(size_t)lr * HID + kb + lk + h];
            As[lk+h+0][lr] = va.x; As[lk+h+1][lr] = va.y;
            As[lk+h+2][lr] = va.z; As[lk+h+3][lr] = va.w;
        }
        {
            float4 vw = *(const float4*)&W[(size_t)(j0 + wj) * HID + kb + wk];
            Ws[wk+0][wj] = vw.x; Ws[wk+1][wj] = vw.y;
            Ws[wk+2][wj] = vw.z; Ws[wk+3][wj] = vw.w;
        }
        __syncthreads();

        #pragma unroll
        for (int k = 0; k < 32; ++k) {   // ascending k
            float4 w = *(const float4*)&Ws[k][tx << 2];
            float a0 = As[k][ty*2 + 0];
            float a1 = As[k][ty*2 + 1];
            acc[0][0] = __fmaf_rn(a0, w.x, acc[0][0]);
            acc[0][1] = __fmaf_rn(a0, w.y, acc[0][1]);
            acc[0][2] = __fmaf_rn(a0, w.z, acc[0][2]);
            acc[0][3] = __fmaf_rn(a0, w.w, acc[0][3]);
            acc[1][0] = __fmaf_rn(a1, w.x, acc[1][0]);
            acc[1][1] = __fmaf_rn(a1, w.y, acc[1][1]);
            acc[1][2] = __fmaf_rn(a1, w.z, acc[1][2]);
            acc[1][3] = __fmaf_rn(a1, w.w, acc[1][3]);
        }
        __syncthreads();
    }

    #pragma unroll
    for (int i = 0; i < 2; ++i)
        #pragma unroll
        for (int j = 0; j < 4; ++j) {
            float v = acc[i][j];
            int col = j0 + (tx << 2) + j;
            if (bias) v = __fadd_rn(v, bias[col]);
            out[(size_t)(ty*2 + i) * HID + col] = v;
        }
}

// s1: p=0: h0@Wh0^T -> p0 (raw) ; p=1: h0@Wy0^T + by0 -> y0 ; p=2: h1@Wh1^T -> p2 (raw)
__global__ __launch_bounds__(256)
void step_s1(const float* __restrict__ h0, const float* __restrict__ h1,
             const float* __restrict__ Wh0, const float* __restrict__ Wy0,
             const float* __restrict__ Wh1, const float* __restrict__ by0)
{
    const int p  = blockIdx.x >> 5;
    const int j0 = (blockIdx.x & 31) << 5;
    const float* A = (p == 2) ? h1 : h0;
    const float* W = (p == 0) ? Wh0 : (p == 1) ? Wy0 : Wh1;
    const float* bias = (p == 1) ? by0 : nullptr;
    float* out = (p == 0) ? g_p0 : (p == 1) ? g_y0 : g_p2;
    small_gemm_tile(A, W, bias, out, j0);
}

// s1b: p1 = y0 @ Wx1^T   (raw, bias applied last in s2)
__global__ __launch_bounds__(256)
void step_s1b(const float* __restrict__ Wx1)
{
    small_gemm_tile(g_y0, Wx1, nullptr, g_p1, blockIdx.x << 5);
}

// s2 — reference add order:
//   h0n = tanh((x@Wx0^T + h0@Wh0^T) + bh0)
//   h1n = tanh((y0@Wx1^T + h1@Wh1^T) + bh1)
__global__ void step_s2(const float* __restrict__ Xp_t,
                        const float* __restrict__ bh0, const float* __restrict__ bh1,
                        float* __restrict__ h0n, float* __restrict__ h1n)
{
    int idx = blockIdx.x * 256 + threadIdx.x;   // 0 .. 2*SB-1
    int b   = idx >> 11;
    int col = idx & 2047;
    int o = b * HID;
    if (col < HID) {
        float v = __fadd_rn(__fadd_rn(Xp_t[o + col], g_p0[o + col]), bh0[col]);
        h0n[o + col] = xla_tanh(v);
    } else {
        int j = col - HID;
        float v = __fadd_rn(__fadd_rn(g_p1[o + j], g_p2[o + j]), bh1[j]);
        h1n[o + j] = xla_tanh(v);
    }
}

__global__ void prologue(const float* __restrict__ hidden,
                         float* __restrict__ h0b, float* __restrict__ h1b)
{
    int i = blockIdx.x * 256 + threadIdx.x;
    h0b[i] = hidden[i];
    h1b[i] = hidden[SB + i];
}

__global__ void tail(const float* __restrict__ h0f, const float* __restrict__ h1f,
                     float* __restrict__ out)
{
    int i = blockIdx.x * 256 + threadIdx.x;
    out[i]      = h0f[i];
    out[SB + i] = h1f[i];
}

// ---------------- launcher ---------------------------------------------------
extern "C" void kernel_launch(void* const* d_in, const int* in_sizes, int n_in,
                              void* d_out, int out_size)
{
    const int*   tok    = (const int*)  d_in[0];
    const float* hidden = (const float*)d_in[1];
    const float* emb    = (const float*)d_in[2];
    const float* Wx0    = (const float*)d_in[3];
    const float* Wh0    = (const float*)d_in[4];
    const float* bh0    = (const float*)d_in[5];
    const float* Wy0    = (const float*)d_in[6];
    const float* by0    = (const float*)d_in[7];
    const float* Wx1    = (const float*)d_in[8];
    const float* Wh1    = (const float*)d_in[9];
    const float* bh1    = (const float*)d_in[10];
    const float* Wy1    = (const float*)d_in[11];
    const float* by1    = (const float*)d_in[12];
    (void)in_sizes; (void)n_in;

    float *Xp, *H1, *h0;
    cudaGetSymbolAddress((void**)&Xp, g_Xp);
    cudaGetSymbolAddress((void**)&H1, g_H1);
    cudaGetSymbolAddress((void**)&h0, g_h0);

    // 1) Xp = gather(emb, tok) @ Wx0^T   (raw — no bias)
    gemm64t<true, false><<<dim3(HID/64, TB/64), 256>>>(
        emb, Wx0, nullptr, tok, Xp, TB, HID, HID);

    // 2) initial states
    prologue<<<SB/256, 256>>>(hidden, h0, H1);

    // 3) sequential scan
    for (int t = 0; t < SEQ; ++t) {
        step_s1 <<<96, 256>>>(h0 + (t & 1) * SB, H1 + (size_t)t * SB,
                              Wh0, Wy0, Wh1, by0);
        step_s1b<<<32, 256>>>(Wx1);
        step_s2 <<<2 * SB / 256, 256>>>(Xp + (size_t)t * SB, bh0, bh1,
                                        h0 + ((t + 1) & 1) * SB,
                                        H1 + (size_t)(t + 1) * SB);
    }

    // 4) logits = H1[0:128] @ Wy1^T + by1
    gemm64t<false, true><<<dim3((VOCAB + 63) / 64, TB / 64), 256>>>(
        H1, Wy1, by1, nullptr, (float*)d_out, TB, VOCAB, HID);

    // 5) final hidden states appended if the out buffer includes them
    long total = (long)TB * VOCAB + 2L * SB;
    if ((long)out_size >= total)
        tail<<<SB/256, 256>>>(h0, H1 + (size_t)SEQ * SB,
                              (float*)d_out + (size_t)TB * VOCAB);
}

// round 12
// speedup vs baseline: 1.3565x; 1.3565x over previous
#include <cuda_runtime.h>
#include <mma.h>
#include <math.h>
#include <stdint.h>

#define SEQ   128
#define BATCH 64
#define HID   1024
#define VOCAB 10000
#define NPAD  10112              /* 79 * 128 */
#define TB    (SEQ*BATCH)        /* 8192 */
#define SB    (BATCH*HID)        /* 65536 */

// ---------------- device scratch (no allocations allowed) -------------------
__device__ float g_Xp[TB*HID];          // RAW x_t @ Wx0^T (no bias), all steps
__device__ float g_H1[(SEQ+1)*SB];      // slot t = h1 entering step t
__device__ float g_h0[2*SB];            // h0 ping-pong
__device__ float g_Wc[HID*HID];         // Wx1 @ Wy0
__device__ float g_Wy0T[HID*HID];       // Wy0 transposed
__device__ float g_cb1[HID];            // bh1 + Wx1 @ by0
__device__ float g_Wy1p[NPAD*HID];      // zero-padded Wy1

// ---------------- XLA EmitFastTanh, FMA-contracted (verified passing) --------
__device__ __forceinline__ float xla_tanh(float x)
{
    const float kClamp = 7.90531110763549805f;
    float xc = fminf(fmaxf(x, -kClamp), kClamp);
    float x2 = __fmul_rn(xc, xc);
    float n = __fmaf_rn(x2, -2.76076847742355e-16f, 2.00018790482477e-13f);
    n = __fmaf_rn(x2, n, -8.60467152213735e-11f);
    n = __fmaf_rn(x2, n,  5.12229709037114e-08f);
    n = __fmaf_rn(x2, n,  1.48572235717979e-05f);
    n = __fmaf_rn(x2, n,  6.37261928875436e-04f);
    n = __fmaf_rn(x2, n,  4.89352455891786e-03f);
    n = __fmul_rn(xc, n);
    float d = __fmaf_rn(x2, 1.19825839466702e-06f, 1.18534705686654e-04f);
    d = __fmaf_rn(x2, d, 2.26843463243900e-03f);
    d = __fmaf_rn(x2, d, 4.89352518554385e-03f);
    return (fabsf(x) < 0.0004f) ? x : __fdiv_rn(n, d);
}

// ---------------- 64x64x16 GEMM: C = op(A) @ B^T (+bias) --------------------
// Bit-exact per-output ascending-k FMA chain (verified passing). B is [N,K].
template<bool GATHER, bool BIAS>
__global__ __launch_bounds__(256)
void gemm64t(const float* __restrict__ A, const float* __restrict__ B,
             const float* __restrict__ bias, const int* __restrict__ gidx,
             float* __restrict__ C, int M, int N, int K)
{
    __shared__ float As[16][64];
    __shared__ float Bs[16][64];

    const int tid = threadIdx.x;
    const int bm = blockIdx.y * 64;
    const int bn = blockIdx.x * 64;
    const int tx = tid & 15;
    const int ty = tid >> 4;
    const int lr = tid >> 2;
    const int lk = (tid & 3) << 2;

    const bool a_ok = (bm + lr) < M;
    size_t arow = 0;
    if (a_ok) {
        if (GATHER) {
            int gi = gidx[bm + lr];
            if ((unsigned)gi >= (unsigned)VOCAB) gi = 0;
            arow = (size_t)gi;
        } else {
            arow = (size_t)(bm + lr);
        }
    }
    const float* Ap = A + arow * (size_t)K + lk;

    const bool b_ok = (bn + lr) < N;
    const float* Bp = B + (size_t)(b_ok ? (bn + lr) : 0) * K + lk;

    float acc[4][4] = {{0.f}};

    for (int k0 = 0; k0 < K; k0 += 16) {
        float4 va = make_float4(0.f, 0.f, 0.f, 0.f);
        if (a_ok) va = *(const float4*)(Ap + k0);
        As[lk+0][lr] = va.x; As[lk+1][lr] = va.y;
        As[lk+2][lr] = va.z; As[lk+3][lr] = va.w;

        float4 vb = make_float4(0.f, 0.f, 0.f, 0.f);
        if (b_ok) vb = *(const float4*)(Bp + k0);
        Bs[lk+0][lr] = vb.x; Bs[lk+1][lr] = vb.y;
        Bs[lk+2][lr] = vb.z; Bs[lk+3][lr] = vb.w;
        __syncthreads();

        #pragma unroll
        for (int k = 0; k < 16; ++k) {
            float4 a = *(const float4*)&As[k][ty << 2];
            float4 b = *(const float4*)&Bs[k][tx << 2];
            float av[4] = {a.x, a.y, a.z, a.w};
            float bv[4] = {b.x, b.y, b.z, b.w};
            #pragma unroll
            for (int i = 0; i < 4; ++i)
                #pragma unroll
                for (int j = 0; j < 4; ++j)
                    acc[i][j] = __fmaf_rn(av[i], bv[j], acc[i][j]);
        }
        __syncthreads();
    }

    #pragma unroll
    for (int i = 0; i < 4; ++i) {
        int gr = bm + (ty << 2) + i;
        if (gr >= M) continue;
        size_t ro = (size_t)gr * N;
        #pragma unroll
        for (int j = 0; j < 4; ++j) {
            int gc = bn + (tx << 2) + j;
            if (gc < N) {
                float v = acc[i][j];
                if (BIAS) v = __fadd_rn(v, bias[gc]);
                C[ro + gc] = v;
            }
        }
    }
}

// ---------------- fused per-step scan kernel ---------------------------------
// grid 96: CTAs 0..31  -> layer 0, 64x32 tile  (BIT-EXACT path)
//          CTAs 32..95 -> layer 1, 64x16 tile, two products (tolerant path)
__global__ __launch_bounds__(256)
void step_fused(const float* __restrict__ h0_in, const float* __restrict__ h1_in,
                const float* __restrict__ Xp_t,
                const float* __restrict__ Wh0, const float* __restrict__ Wh1,
                const float* __restrict__ bh0,
                float* __restrict__ h0_out, float* __restrict__ h1_out)
{
    __shared__ float As[32][64];
    __shared__ float As2[32][64];
    __shared__ float Wb[32][40];

    const int tid = threadIdx.x;
    const int bid = blockIdx.x;

    if (bid < 32) {
        // ======== layer 0: exact replication of passing small_gemm_tile ========
        const int j0 = bid << 5;
        const int tx = tid & 7;
        const int ty = tid >> 3;
        const int lr = tid >> 2;
        const int lk = (tid & 3) << 2;
        const int wj = tid >> 3;
        const int wk = (tid & 7) << 2;

        float acc[2][4] = {{0.f}};

        for (int kb = 0; kb < HID; kb += 32) {
            #pragma unroll
            for (int h = 0; h < 32; h += 16) {
                float4 va = *(const float4*)&h0_in[(size_t)lr * HID + kb + lk + h];
                As[lk+h+0][lr] = va.x; As[lk+h+1][lr] = va.y;
                As[lk+h+2][lr] = va.z; As[lk+h+3][lr] = va.w;
            }
            {
                float4 vw = *(const float4*)&Wh0[(size_t)(j0 + wj) * HID + kb + wk];
                Wb[wk+0][wj] = vw.x; Wb[wk+1][wj] = vw.y;
                Wb[wk+2][wj] = vw.z; Wb[wk+3][wj] = vw.w;
            }
            __syncthreads();

            #pragma unroll
            for (int k = 0; k < 32; ++k) {   // ascending k — unchanged chain
                float4 w = *(const float4*)&Wb[k][tx << 2];
                float a0 = As[k][ty*2 + 0];
                float a1 = As[k][ty*2 + 1];
                acc[0][0] = __fmaf_rn(a0, w.x, acc[0][0]);
                acc[0][1] = __fmaf_rn(a0, w.y, acc[0][1]);
                acc[0][2] = __fmaf_rn(a0, w.z, acc[0][2]);
                acc[0][3] = __fmaf_rn(a0, w.w, acc[0][3]);
                acc[1][0] = __fmaf_rn(a1, w.x, acc[1][0]);
                acc[1][1] = __fmaf_rn(a1, w.y, acc[1][1]);
                acc[1][2] = __fmaf_rn(a1, w.z, acc[1][2]);
                acc[1][3] = __fmaf_rn(a1, w.w, acc[1][3]);
            }
            __syncthreads();
        }

        // epilogue — identical arithmetic to old step_s2: tanh((Xp + p0) + bh0)
        #pragma unroll
        for (int i = 0; i < 2; ++i)
            #pragma unroll
            for (int j = 0; j < 4; ++j) {
                int row = ty*2 + i;
                int col = j0 + (tx << 2) + j;
                float v = __fadd_rn(__fadd_rn(Xp_t[(size_t)row * HID + col],
                                              acc[i][j]), bh0[col]);
                h0_out[(size_t)row * HID + col] = xla_tanh(v);
            }
    } else {
        // ======== layer 1 (tolerant): pc = h0@Wc^T, p2 = h1@Wh1^T ========
        const int j0 = (bid - 32) << 4;       // 16-col tile
        const int tx = tid & 3;               // col group (4 cols)
        const int ty = tid >> 2;              // row 0..63
        const int lr = tid >> 2;
        const int lk = (tid & 3) << 2;

        float accC[4] = {0.f, 0.f, 0.f, 0.f};
        float accH[4] = {0.f, 0.f, 0.f, 0.f};

        for (int kb = 0; kb < HID; kb += 32) {
            #pragma unroll
            for (int h = 0; h < 32; h += 16) {
                float4 v0 = *(const float4*)&h0_in[(size_t)lr * HID + kb + lk + h];
                As[lk+h+0][lr] = v0.x; As[lk+h+1][lr] = v0.y;
                As[lk+h+2][lr] = v0.z; As[lk+h+3][lr] = v0.w;
                float4 v1 = *(const float4*)&h1_in[(size_t)lr * HID + kb + lk + h];
                As2[lk+h+0][lr] = v1.x; As2[lk+h+1][lr] = v1.y;
                As2[lk+h+2][lr] = v1.z; As2[lk+h+3][lr] = v1.w;
            }
            {
                int half = tid >> 7;              // 0 -> Wc, 1 -> Wh1
                int t    = tid & 127;
                int row  = t >> 3;                // 0..15
                int kc   = (t & 7) << 2;          // 0..28
                const float* Wsrc = half ? Wh1 : g_Wc;
                float4 w = *(const float4*)&Wsrc[(size_t)(j0 + row) * HID + kb + kc];
                int base = half ? 20 : 0;
                Wb[kc+0][base + row] = w.x; Wb[kc+1][base + row] = w.y;
                Wb[kc+2][base + row] = w.z; Wb[kc+3][base + row] = w.w;
            }
            __syncthreads();

            #pragma unroll
            for (int k = 0; k < 32; ++k) {
                float a0 = As[k][ty];
                float a1 = As2[k][ty];
                float4 wc = *(const float4*)&Wb[k][tx << 2];
                float4 wh = *(const float4*)&Wb[k][20 + (tx << 2)];
                accC[0] = __fmaf_rn(a0, wc.x, accC[0]);
                accC[1] = __fmaf_rn(a0, wc.y, accC[1]);
                accC[2] = __fmaf_rn(a0, wc.z, accC[2]);
                accC[3] = __fmaf_rn(a0, wc.w, accC[3]);
                accH[0] = __fmaf_rn(a1, wh.x, accH[0]);
                accH[1] = __fmaf_rn(a1, wh.y, accH[1]);
                accH[2] = __fmaf_rn(a1, wh.z, accH[2]);
                accH[3] = __fmaf_rn(a1, wh.w, accH[3]);
            }
            __syncthreads();
        }

        #pragma unroll
        for (int j = 0; j < 4; ++j) {
            int col = j0 + (tx << 2) + j;
            float v = __fadd_rn(__fadd_rn(accC[j], accH[j]), g_cb1[col]);
            h1_out[(size_t)ty * HID + col] = xla_tanh(v);
        }
    }
}

// ---------------- TF32 wmma logits: out = H1 @ Wy1p^T + by1 ------------------
__global__ __launch_bounds__(256)
void logits_wmma(const float* __restrict__ H1all, const float* __restrict__ by1,
                 float* __restrict__ out)
{
    using namespace nvcuda;
    __shared__ float As[128][36];
    __shared__ float Bs[128][36];
    __shared__ float st[8][16*20];

    const int tid  = threadIdx.x;
    const int wid  = tid >> 5;
    const int lane = tid & 31;
    const int bm = blockIdx.y * 128;
    const int bn = blockIdx.x * 128;
    const int wm = (wid >> 1) * 32;   // warp m offset (4 rows of warps)
    const int wn = (wid & 1) * 64;    // warp n offset (2 cols of warps)

    wmma::fragment<wmma::accumulator, 16, 16, 8, float> acc[2][4];
    #pragma unroll
    for (int mi = 0; mi < 2; ++mi)
        #pragma unroll
        for (int ni = 0; ni < 4; ++ni)
            wmma::fill_fragment(acc[mi][ni], 0.f);

    for (int k0 = 0; k0 < HID; k0 += 32) {
        #pragma unroll
        for (int u = 0; u < 4; ++u) {
            int r  = (tid >> 3) + u * 32;
            int kc = (tid & 7) << 2;
            float4 v = *(const float4*)(H1all + (size_t)(bm + r) * HID + k0 + kc);
            As[r][kc+0] = v.x; As[r][kc+1] = v.y; As[r][kc+2] = v.z; As[r][kc+3] = v.w;
            float4 w = *(const float4*)(g_Wy1p + (size_t)(bn + r) * HID + k0 + kc);
            Bs[r][kc+0] = w.x; Bs[r][kc+1] = w.y; Bs[r][kc+2] = w.z; Bs[r][kc+3] = w.w;
        }
        __syncthreads();

        #pragma unroll
        for (int ks = 0; ks < 32; ks += 8) {
            wmma::fragment<wmma::matrix_a, 16, 16, 8, wmma::precision::tf32, wmma::row_major> af[2];
            wmma::fragment<wmma::matrix_b, 16, 16, 8, wmma::precision::tf32, wmma::col_major> bf[4];
            #pragma unroll
            for (int mi = 0; mi < 2; ++mi) {
                wmma::load_matrix_sync(af[mi], &As[wm + mi*16][ks], 36);
                #pragma unroll
                for (int e = 0; e < af[mi].num_elements; ++e)
                    af[mi].x[e] = wmma::__float_to_tf32(af[mi].x[e]);
            }
            #pragma unroll
            for (int ni = 0; ni < 4; ++ni) {
                wmma::load_matrix_sync(bf[ni], &Bs[wn + ni*16][ks], 36);
                #pragma unroll
                for (int e = 0; e < bf[ni].num_elements; ++e)
                    bf[ni].x[e] = wmma::__float_to_tf32(bf[ni].x[e]);
            }
            #pragma unroll
            for (int mi = 0; mi < 2; ++mi)
                #pragma unroll
                for (int ni = 0; ni < 4; ++ni)
                    wmma::mma_sync(acc[mi][ni], af[mi], bf[ni], acc[mi][ni]);
        }
        __syncthreads();
    }

    // epilogue: per-warp staging, guarded store with bias
    #pragma unroll
    for (int mi = 0; mi < 2; ++mi)
        #pragma unroll
        for (int ni = 0; ni < 4; ++ni) {
            wmma::store_matrix_sync(&st[wid][0], acc[mi][ni], 20, wmma::mem_row_major);
            __syncwarp();
            #pragma unroll
            for (int e = 0; e < 8; ++e) {
                int idx = e * 32 + lane;
                int r = idx >> 4, c = idx & 15;
                int gr = bm + wm + mi*16 + r;
                int gc = bn + wn + ni*16 + c;
                if (gc < VOCAB)
                    out[(size_t)gr * VOCAB + gc] = __fadd_rn(st[wid][r*20 + c], by1[gc]);
            }
            __syncwarp();
        }
}

// ---------------- small helper kernels ---------------------------------------
__global__ void pad_wy1(const float* __restrict__ Wy1)
{
    size_t idx = (size_t)blockIdx.x * 256 + threadIdx.x;   // NPAD*HID total
    int n = (int)(idx >> 10);
    g_Wy1p[idx] = (n < VOCAB) ? Wy1[idx - ((size_t)(n - n) )*0 + ((size_t)n*HID + (idx & 1023)) - idx + idx] : 0.f;
}

__global__ void pad_wy1_fix(const float* __restrict__ Wy1)
{
    size_t idx = (size_t)blockIdx.x * 256 + threadIdx.x;
    int n = (int)(idx >> 10);
    int k = (int)(idx & 1023);
    g_Wy1p[idx] = (n < VOCAB) ? Wy1[(size_t)n * HID + k] : 0.f;
}

__global__ void transpose_wy0(const float* __restrict__ Wy0)
{
    int idx = blockIdx.x * 256 + threadIdx.x;   // 0 .. HID*HID-1
    int j = idx >> 10, k = idx & 1023;
    g_Wy0T[(size_t)j * HID + k] = Wy0[(size_t)k * HID + j];
}

__global__ void cb1_kernel(const float* __restrict__ bh1, const float* __restrict__ by0,
                           const float* __restrict__ Wx1)
{
    int j = blockIdx.x;
    const float* row = Wx1 + (size_t)j * HID;
    float s = 0.f;
    for (int k = threadIdx.x; k < HID; k += 128) s += by0[k] * row[k];
    for (int off = 16; off > 0; off >>= 1) s += __shfl_xor_sync(0xffffffffu, s, off);
    __shared__ float ws[4];
    if ((threadIdx.x & 31) == 0) ws[threadIdx.x >> 5] = s;
    __syncthreads();
    if (threadIdx.x == 0) g_cb1[j] = ws[0] + ws[1] + ws[2] + ws[3] + bh1[j];
}

__global__ void prologue(const float* __restrict__ hidden,
                         float* __restrict__ h0b, float* __restrict__ h1b)
{
    int i = blockIdx.x * 256 + threadIdx.x;
    h0b[i] = hidden[i];
    h1b[i] = hidden[SB + i];
}

__global__ void tail(const float* __restrict__ h0f, const float* __restrict__ h1f,
                     float* __restrict__ out)
{
    int i = blockIdx.x * 256 + threadIdx.x;
    out[i]      = h0f[i];
    out[SB + i] = h1f[i];
}

// ---------------- launcher ---------------------------------------------------
extern "C" void kernel_launch(void* const* d_in, const int* in_sizes, int n_in,
                              void* d_out, int out_size)
{
    const int*   tok    = (const int*)  d_in[0];
    const float* hidden = (const float*)d_in[1];
    const float* emb    = (const float*)d_in[2];
    const float* Wx0    = (const float*)d_in[3];
    const float* Wh0    = (const float*)d_in[4];
    const float* bh0    = (const float*)d_in[5];
    const float* Wy0    = (const float*)d_in[6];
    const float* by0    = (const float*)d_in[7];
    const float* Wx1    = (const float*)d_in[8];
    const float* Wh1    = (const float*)d_in[9];
    const float* bh1    = (const float*)d_in[10];
    const float* Wy1    = (const float*)d_in[11];
    const float* by1    = (const float*)d_in[12];
    (void)in_sizes; (void)n_in;

    float *Xp, *H1, *h0, *WcP, *Wy0T;
    cudaGetSymbolAddress((void**)&Xp,   g_Xp);
    cudaGetSymbolAddress((void**)&H1,   g_H1);
    cudaGetSymbolAddress((void**)&h0,   g_h0);
    cudaGetSymbolAddress((void**)&WcP,  g_Wc);
    cudaGetSymbolAddress((void**)&Wy0T, g_Wy0T);

    // 1) Xp = gather(emb, tok) @ Wx0^T   (raw, BIT-EXACT path — unchanged)
    gemm64t<true, false><<<dim3(HID/64, TB/64), 256>>>(
        emb, Wx0, nullptr, tok, Xp, TB, HID, HID);

    // 2) precompute (tolerant h1 path): Wy0T, Wc = Wx1 @ Wy0, cb1; pad Wy1
    transpose_wy0<<<HID*HID/256, 256>>>(Wy0);
    gemm64t<false, false><<<dim3(HID/64, HID/64), 256>>>(
        Wx1, Wy0T, nullptr, nullptr, WcP, HID, HID, HID);
    cb1_kernel<<<HID, 128>>>(bh1, by0, Wx1);
    pad_wy1_fix<<<(NPAD*HID)/256, 256>>>(Wy1);

    // 3) initial states
    prologue<<<SB/256, 256>>>(hidden, h0, H1);

    // 4) sequential scan — ONE launch per step
    for (int t = 0; t < SEQ; ++t) {
        step_fused<<<96, 256>>>(h0 + (t & 1) * SB, H1 + (size_t)t * SB,
                                Xp + (size_t)t * SB,
                                Wh0, Wh1, bh0,
                                h0 + ((t + 1) & 1) * SB,
                                H1 + (size_t)(t + 1) * SB);
    }

    // 5) logits = H1[0:128] @ Wy1^T + by1   (TF32 tensor cores)
    logits_wmma<<<dim3(NPAD/128, TB/128), 256>>>(H1, by1, (float*)d_out);

    // 6) final hidden states appended if out buffer includes them
    long total = (long)TB * VOCAB + 2L * SB;
    if ((long)out_size >= total)
        tail<<<SB/256, 256>>>(h0, H1 + (size_t)SEQ * SB,
                              (float*)d_out + (size_t)TB * VOCAB);
}

// round 13
// speedup vs baseline: 1.4834x; 1.0936x over previous
#include <cuda_runtime.h>
#include <mma.h>
#include <math.h>
#include <stdint.h>

#define SEQ   128
#define BATCH 64
#define HID   1024
#define VOCAB 10000
#define NPAD  10112              /* 79 * 128 */
#define TB    (SEQ*BATCH)        /* 8192 */
#define SB    (BATCH*HID)        /* 65536 */
#define NCTA  128                /* persistent scan grid (<= 148 SMs) */

// ---------------- device scratch (no allocations allowed) -------------------
__device__ float g_Xp[TB*HID];          // RAW x_t @ Wx0^T (no bias), all steps
__device__ float g_H1[(SEQ+1)*SB];      // slot t = h1 entering step t
__device__ float g_h0[2*SB];            // h0 ping-pong
__device__ float g_Wc[HID*HID];         // Wx1 @ Wy0
__device__ float g_Wy0T[HID*HID];       // Wy0 transposed
__device__ float g_cb1[HID];            // bh1 + Wx1 @ by0
__device__ float g_Wy1p[NPAD*HID];      // zero-padded Wy1

// persistent-scan barrier state
__device__ unsigned g_bar_count;
__device__ volatile unsigned g_bar_gen;

// ---------------- XLA EmitFastTanh, FMA-contracted (verified passing) --------
__device__ __forceinline__ float xla_tanh(float x)
{
    const float kClamp = 7.90531110763549805f;
    float xc = fminf(fmaxf(x, -kClamp), kClamp);
    float x2 = __fmul_rn(xc, xc);
    float n = __fmaf_rn(x2, -2.76076847742355e-16f, 2.00018790482477e-13f);
    n = __fmaf_rn(x2, n, -8.60467152213735e-11f);
    n = __fmaf_rn(x2, n,  5.12229709037114e-08f);
    n = __fmaf_rn(x2, n,  1.48572235717979e-05f);
    n = __fmaf_rn(x2, n,  6.37261928875436e-04f);
    n = __fmaf_rn(x2, n,  4.89352455891786e-03f);
    n = __fmul_rn(xc, n);
    float d = __fmaf_rn(x2, 1.19825839466702e-06f, 1.18534705686654e-04f);
    d = __fmaf_rn(x2, d, 2.26843463243900e-03f);
    d = __fmaf_rn(x2, d, 4.89352518554385e-03f);
    return (fabsf(x) < 0.0004f) ? x : __fdiv_rn(n, d);
}

// ---------------- 64x64x16 GEMM: C = op(A) @ B^T (+bias) --------------------
// Bit-exact per-output ascending-k FMA chain (verified passing). B is [N,K].
template<bool GATHER, bool BIAS>
__global__ __launch_bounds__(256)
void gemm64t(const float* __restrict__ A, const float* __restrict__ B,
             const float* __restrict__ bias, const int* __restrict__ gidx,
             float* __restrict__ C, int M, int N, int K)
{
    __shared__ float As[16][64];
    __shared__ float Bs[16][64];

    const int tid = threadIdx.x;
    const int bm = blockIdx.y * 64;
    const int bn = blockIdx.x * 64;
    const int tx = tid & 15;
    const int ty = tid >> 4;
    const int lr = tid >> 2;
    const int lk = (tid & 3) << 2;

    const bool a_ok = (bm + lr) < M;
    size_t arow = 0;
    if (a_ok) {
        if (GATHER) {
            int gi = gidx[bm + lr];
            if ((unsigned)gi >= (unsigned)VOCAB) gi = 0;
            arow = (size_t)gi;
        } else {
            arow = (size_t)(bm + lr);
        }
    }
    const float* Ap = A + arow * (size_t)K + lk;

    const bool b_ok = (bn + lr) < N;
    const float* Bp = B + (size_t)(b_ok ? (bn + lr) : 0) * K + lk;

    float acc[4][4] = {{0.f}};

    for (int k0 = 0; k0 < K; k0 += 16) {
        float4 va = make_float4(0.f, 0.f, 0.f, 0.f);
        if (a_ok) va = *(const float4*)(Ap + k0);
        As[lk+0][lr] = va.x; As[lk+1][lr] = va.y;
        As[lk+2][lr] = va.z; As[lk+3][lr] = va.w;

        float4 vb = make_float4(0.f, 0.f, 0.f, 0.f);
        if (b_ok) vb = *(const float4*)(Bp + k0);
        Bs[lk+0][lr] = vb.x; Bs[lk+1][lr] = vb.y;
        Bs[lk+2][lr] = vb.z; Bs[lk+3][lr] = vb.w;
        __syncthreads();

        #pragma unroll
        for (int k = 0; k < 16; ++k) {
            float4 a = *(const float4*)&As[k][ty << 2];
            float4 b = *(const float4*)&Bs[k][tx << 2];
            float av[4] = {a.x, a.y, a.z, a.w};
            float bv[4] = {b.x, b.y, b.z, b.w};
            #pragma unroll
            for (int i = 0; i < 4; ++i)
                #pragma unroll
                for (int j = 0; j < 4; ++j)
                    acc[i][j] = __fmaf_rn(av[i], bv[j], acc[i][j]);
        }
        __syncthreads();
    }

    #pragma unroll
    for (int i = 0; i < 4; ++i) {
        int gr = bm + (ty << 2) + i;
        if (gr >= M) continue;
        size_t ro = (size_t)gr * N;
        #pragma unroll
        for (int j = 0; j < 4; ++j) {
            int gc = bn + (tx << 2) + j;
            if (gc < N) {
                float v = acc[i][j];
                if (BIAS) v = __fadd_rn(v, bias[gc]);
                C[ro + gc] = v;
            }
        }
    }
}

// ---------------- persistent scan kernel -------------------------------------
// Grid = NCTA (co-resident). CTA c owns 8 cols [8c, 8c+8) of Wh0, Wc, Wh1
// (smem-resident for all 128 steps). One global barrier per step.
__device__ __forceinline__ void grid_barrier()
{
    __syncthreads();
    if (threadIdx.x == 0) {
        __threadfence();
        unsigned gen = g_bar_gen;
        if (atomicAdd(&g_bar_count, 1u) == NCTA - 1) {
            *(volatile unsigned*)&g_bar_count = 0;
            __threadfence();
            g_bar_gen = gen + 1;
        } else {
            while (g_bar_gen == gen) __nanosleep(32);
        }
        __threadfence();
    }
    __syncthreads();
}

__global__ __launch_bounds__(256, 1)
void scan_persistent(const float* __restrict__ Wh0, const float* __restrict__ Wh1,
                     const float* __restrict__ bh0)
{
    extern __shared__ float sm[];
    float* w0  = sm;              // [1024][8]  Wh0 slice, [k][c]
    float* wc  = sm + 8192;       // [1024][8]  Wc slice
    float* wh  = sm + 16384;      // [1024][8]  Wh1 slice
    float* As  = sm + 24576;      // [32][64]   h0 staging, [k][row]
    float* As2 = sm + 26624;      // [32][64]   h1 staging

    const int tid = threadIdx.x;
    const int bid = blockIdx.x;
    const int j0  = bid << 3;          // global col base (8 cols)
    const int r   = tid >> 2;          // output row 0..63
    const int cg  = tid & 3;           // col group (2 cols)
    const int lc  = cg << 1;           // local col 0,2,4,6

    // load weight slices once (transposed to [k][c])
    for (int i = tid; i < 8 * HID; i += 256) {
        int j = i >> 10;               // 0..7
        int k = i & 1023;
        w0[k*8 + j] = Wh0 [(size_t)(j0 + j) * HID + k];
        wc[k*8 + j] = g_Wc[(size_t)(j0 + j) * HID + k];
        wh[k*8 + j] = Wh1 [(size_t)(j0 + j) * HID + k];
    }
    float bh0c0 = bh0[j0 + lc], bh0c1 = bh0[j0 + lc + 1];
    float cb1c0 = g_cb1[j0 + lc], cb1c1 = g_cb1[j0 + lc + 1];

    const int lr = tid >> 2;           // staging row 0..63
    const int lk = (tid & 3) << 2;     // staging k offset 0..12

    grid_barrier();   // weights + precomputed Wc/cb1 visible everywhere

    for (int t = 0; t < SEQ; ++t) {
        const float* h0_in = g_h0 + (size_t)(t & 1) * SB;
        const float* h1_in = g_H1 + (size_t)t * SB;
        const float* Xp_t  = g_Xp + (size_t)t * SB;
        float* h0_out = g_h0 + (size_t)((t + 1) & 1) * SB;
        float* h1_out = g_H1 + (size_t)(t + 1) * SB;

        float a00 = 0.f, a01 = 0.f;    // p0 = h0 @ Wh0^T  (BIT-EXACT chain)
        float c00 = 0.f, c01 = 0.f;    // pc = h0 @ Wc^T
        float h00 = 0.f, h01 = 0.f;    // ph = h1 @ Wh1^T

        for (int kb = 0; kb < HID; kb += 32) {
            #pragma unroll
            for (int h = 0; h < 32; h += 16) {
                float4 v0 = __ldcg((const float4*)&h0_in[(size_t)lr * HID + kb + lk + h]);
                As[(lk+h+0)*64 + lr] = v0.x; As[(lk+h+1)*64 + lr] = v0.y;
                As[(lk+h+2)*64 + lr] = v0.z; As[(lk+h+3)*64 + lr] = v0.w;
                float4 v1 = __ldcg((const float4*)&h1_in[(size_t)lr * HID + kb + lk + h]);
                As2[(lk+h+0)*64 + lr] = v1.x; As2[(lk+h+1)*64 + lr] = v1.y;
                As2[(lk+h+2)*64 + lr] = v1.z; As2[(lk+h+3)*64 + lr] = v1.w;
            }
            __syncthreads();

            #pragma unroll
            for (int k = 0; k < 32; ++k) {   // ascending k — bit-exact chains
                float a0 = As [k*64 + r];
                float a1 = As2[k*64 + r];
                int cb = (kb + k) * 8 + lc;
                float2 W0 = *(const float2*)&w0[cb];
                float2 WC = *(const float2*)&wc[cb];
                float2 WH = *(const float2*)&wh[cb];
                a00 = __fmaf_rn(a0, W0.x, a00);  a01 = __fmaf_rn(a0, W0.y, a01);
                c00 = __fmaf_rn(a0, WC.x, c00);  c01 = __fmaf_rn(a0, WC.y, c01);
                h00 = __fmaf_rn(a1, WH.x, h00);  h01 = __fmaf_rn(a1, WH.y, h01);
            }
            __syncthreads();
        }

        // epilogues (identical arithmetic to validated version)
        {
            size_t o = (size_t)r * HID + j0 + lc;
            float v0 = __fadd_rn(__fadd_rn(Xp_t[o + 0], a00), bh0c0);
            float v1 = __fadd_rn(__fadd_rn(Xp_t[o + 1], a01), bh0c1);
            h0_out[o + 0] = xla_tanh(v0);
            h0_out[o + 1] = xla_tanh(v1);
            float u0 = __fadd_rn(__fadd_rn(c00, h00), cb1c0);
            float u1 = __fadd_rn(__fadd_rn(c01, h01), cb1c1);
            h1_out[o + 0] = xla_tanh(u0);
            h1_out[o + 1] = xla_tanh(u1);
        }

        grid_barrier();
    }
}

// ---------------- TF32 wmma logits: out = H1 @ Wy1p^T + by1 ------------------
__global__ __launch_bounds__(256)
void logits_wmma(const float* __restrict__ H1all, const float* __restrict__ by1,
                 float* __restrict__ out)
{
    using namespace nvcuda;
    __shared__ float As[128][36];
    __shared__ float Bs[128][36];
    __shared__ float st[8][16*20];

    const int tid  = threadIdx.x;
    const int wid  = tid >> 5;
    const int lane = tid & 31;
    const int bm = blockIdx.y * 128;
    const int bn = blockIdx.x * 128;
    const int wm = (wid >> 1) * 32;
    const int wn = (wid & 1) * 64;

    wmma::fragment<wmma::accumulator, 16, 16, 8, float> acc[2][4];
    #pragma unroll
    for (int mi = 0; mi < 2; ++mi)
        #pragma unroll
        for (int ni = 0; ni < 4; ++ni)
            wmma::fill_fragment(acc[mi][ni], 0.f);

    for (int k0 = 0; k0 < HID; k0 += 32) {
        #pragma unroll
        for (int u = 0; u < 4; ++u) {
            int rr = (tid >> 3) + u * 32;
            int kc = (tid & 7) << 2;
            float4 v = *(const float4*)(H1all + (size_t)(bm + rr) * HID + k0 + kc);
            As[rr][kc+0] = v.x; As[rr][kc+1] = v.y; As[rr][kc+2] = v.z; As[rr][kc+3] = v.w;
            float4 w = *(const float4*)(g_Wy1p + (size_t)(bn + rr) * HID + k0 + kc);
            Bs[rr][kc+0] = w.x; Bs[rr][kc+1] = w.y; Bs[rr][kc+2] = w.z; Bs[rr][kc+3] = w.w;
        }
        __syncthreads();

        #pragma unroll
        for (int ks = 0; ks < 32; ks += 8) {
            wmma::fragment<wmma::matrix_a, 16, 16, 8, wmma::precision::tf32, wmma::row_major> af[2];
            wmma::fragment<wmma::matrix_b, 16, 16, 8, wmma::precision::tf32, wmma::col_major> bf[4];
            #pragma unroll
            for (int mi = 0; mi < 2; ++mi) {
                wmma::load_matrix_sync(af[mi], &As[wm + mi*16][ks], 36);
                #pragma unroll
                for (int e = 0; e < af[mi].num_elements; ++e)
                    af[mi].x[e] = wmma::__float_to_tf32(af[mi].x[e]);
            }
            #pragma unroll
            for (int ni = 0; ni < 4; ++ni) {
                wmma::load_matrix_sync(bf[ni], &Bs[wn + ni*16][ks], 36);
                #pragma unroll
                for (int e = 0; e < bf[ni].num_elements; ++e)
                    bf[ni].x[e] = wmma::__float_to_tf32(bf[ni].x[e]);
            }
            #pragma unroll
            for (int mi = 0; mi < 2; ++mi)
                #pragma unroll
                for (int ni = 0; ni < 4; ++ni)
                    wmma::mma_sync(acc[mi][ni], af[mi], bf[ni], acc[mi][ni]);
        }
        __syncthreads();
    }

    #pragma unroll
    for (int mi = 0; mi < 2; ++mi)
        #pragma unroll
        for (int ni = 0; ni < 4; ++ni) {
            wmma::store_matrix_sync(&st[wid][0], acc[mi][ni], 20, wmma::mem_row_major);
            __syncwarp();
            #pragma unroll
            for (int e = 0; e < 8; ++e) {
                int idx = e * 32 + lane;
                int rr = idx >> 4, cc = idx & 15;
                int gr = bm + wm + mi*16 + rr;
                int gc = bn + wn + ni*16 + cc;
                if (gc < VOCAB)
                    out[(size_t)gr * VOCAB + gc] = __fadd_rn(st[wid][rr*20 + cc], by1[gc]);
            }
            __syncwarp();
        }
}

// ---------------- small helper kernels ---------------------------------------
__global__ void pad_wy1_fix(const float* __restrict__ Wy1)
{
    size_t idx = (size_t)blockIdx.x * 256 + threadIdx.x;
    int n = (int)(idx >> 10);
    int k = (int)(idx & 1023);
    g_Wy1p[idx] = (n < VOCAB) ? Wy1[(size_t)n * HID + k] : 0.f;
}

__global__ void transpose_wy0(const float* __restrict__ Wy0)
{
    int idx = blockIdx.x * 256 + threadIdx.x;
    int j = idx >> 10, k = idx & 1023;
    g_Wy0T[(size_t)j * HID + k] = Wy0[(size_t)k * HID + j];
}

__global__ void cb1_kernel(const float* __restrict__ bh1, const float* __restrict__ by0,
                           const float* __restrict__ Wx1)
{
    int j = blockIdx.x;
    const float* row = Wx1 + (size_t)j * HID;
    float s = 0.f;
    for (int k = threadIdx.x; k < HID; k += 128) s += by0[k] * row[k];
    for (int off = 16; off > 0; off >>= 1) s += __shfl_xor_sync(0xffffffffu, s, off);
    __shared__ float ws[4];
    if ((threadIdx.x & 31) == 0) ws[threadIdx.x >> 5] = s;
    __syncthreads();
    if (threadIdx.x == 0) g_cb1[j] = ws[0] + ws[1] + ws[2] + ws[3] + bh1[j];
}

__global__ void prologue(const float* __restrict__ hidden,
                         float* __restrict__ h0b, float* __restrict__ h1b)
{
    int i = blockIdx.x * 256 + threadIdx.x;
    h0b[i] = hidden[i];
    h1b[i] = hidden[SB + i];
}

__global__ void tail(const float* __restrict__ h0f, const float* __restrict__ h1f,
                     float* __restrict__ out)
{
    int i = blockIdx.x * 256 + threadIdx.x;
    out[i]      = h0f[i];
    out[SB + i] = h1f[i];
}

// ---------------- launcher ---------------------------------------------------
extern "C" void kernel_launch(void* const* d_in, const int* in_sizes, int n_in,
                              void* d_out, int out_size)
{
    const int*   tok    = (const int*)  d_in[0];
    const float* hidden = (const float*)d_in[1];
    const float* emb    = (const float*)d_in[2];
    const float* Wx0    = (const float*)d_in[3];
    const float* Wh0    = (const float*)d_in[4];
    const float* bh0    = (const float*)d_in[5];
    const float* Wy0    = (const float*)d_in[6];
    const float* by0    = (const float*)d_in[7];
    const float* Wx1    = (const float*)d_in[8];
    const float* Wh1    = (const float*)d_in[9];
    const float* bh1    = (const float*)d_in[10];
    const float* Wy1    = (const float*)d_in[11];
    const float* by1    = (const float*)d_in[12];
    (void)in_sizes; (void)n_in;

    float *Xp, *H1, *h0, *WcP, *Wy0T;
    cudaGetSymbolAddress((void**)&Xp,   g_Xp);
    cudaGetSymbolAddress((void**)&H1,   g_H1);
    cudaGetSymbolAddress((void**)&h0,   g_h0);
    cudaGetSymbolAddress((void**)&WcP,  g_Wc);
    cudaGetSymbolAddress((void**)&Wy0T, g_Wy0T);

    const int SMEM_SCAN = (3 * 8 * HID + 2 * 32 * 64) * sizeof(float);  // 114688
    cudaFuncSetAttribute(scan_persistent,
                         cudaFuncAttributeMaxDynamicSharedMemorySize, SMEM_SCAN);

    // 1) Xp = gather(emb, tok) @ Wx0^T   (raw, BIT-EXACT path — unchanged)
    gemm64t<true, false><<<dim3(HID/64, TB/64), 256>>>(
        emb, Wx0, nullptr, tok, Xp, TB, HID, HID);

    // 2) precompute (tolerant h1 path): Wy0T, Wc = Wx1 @ Wy0, cb1; pad Wy1
    transpose_wy0<<<HID*HID/256, 256>>>(Wy0);
    gemm64t<false, false><<<dim3(HID/64, HID/64), 256>>>(
        Wx1, Wy0T, nullptr, nullptr, WcP, HID, HID, HID);
    cb1_kernel<<<HID, 128>>>(bh1, by0, Wx1);
    pad_wy1_fix<<<(NPAD*HID)/256, 256>>>(Wy1);

    // 3) initial states
    prologue<<<SB/256, 256>>>(hidden, h0, H1);

    // 4) sequential scan — ONE persistent launch for all 128 steps
    scan_persistent<<<NCTA, 256, SMEM_SCAN>>>(Wh0, Wh1, bh0);

    // 5) logits = H1[0:128] @ Wy1^T + by1   (TF32 tensor cores)
    logits_wmma<<<dim3(NPAD/128, TB/128), 256>>>(H1, by1, (float*)d_out);

    // 6) final hidden states appended if out buffer includes them
    long total = (long)TB * VOCAB + 2L * SB;
    if ((long)out_size >= total)
        tail<<<SB/256, 256>>>(h0, H1 + (size_t)SEQ * SB,
                              (float*)d_out + (size_t)TB * VOCAB);
}